// round 1
// baseline (speedup 1.0000x reference)
#include <cuda_runtime.h>
#include <math.h>

// Problem constants
#define B_   16
#define L_   50
#define P_   49
#define T_   20
#define D_   512
#define H_   8
#define DH_  64
#define DFF_ 2048
#define IMG_TOK (B_*L_*T_)   // 16000 tokens on the title-side output (attends over img)
#define TIT_TOK (B_*L_*P_)   // 39200 tokens on the img-side output (attends over title)
#define NTOK (IMG_TOK + TIT_TOK)  // 55200
#define NEGV (-1000000000.0f)
#define EPS_ 1e-6f

// ---------------- scratch (static device arrays; no cudaMalloc allowed) ----------------
__device__ float g_attn[NTOK * D_];          // attention outputs (img tokens first, then tit)
__device__ float g_hid [NTOK * D_];          // after proj (residual source)
__device__ float g_ffn1[NTOK * DFF_];        // gelu(hid @ w1^T + b1)
__device__ float g_ffn2[NTOK * D_];          // ffn output pre-LN

// ---------------- attention kernel: one block per (b, l, h) ----------------
__global__ void __launch_bounds__(256) attn_kernel(
    const float* __restrict__ img, const float* __restrict__ title,
    const int* __restrict__ mask,
    const float* __restrict__ scale_img, const float* __restrict__ scale_title,
    float* __restrict__ attn)
{
    int blk = blockIdx.x;
    int h  = blk % H_;
    int bl = blk / H_;   // 0..B*L-1

    const float* imgp = img   + (size_t)bl * P_ * D_ + h * DH_;
    const float* titp = title + (size_t)bl * T_ * D_ + h * DH_;
    const int*   mp   = mask  + bl * T_;

    __shared__ float s_img[P_][DH_ + 1];  // padded: conflict-free column reads
    __shared__ float s_tit[T_][DH_ + 1];
    __shared__ float s_raw [P_][T_];
    __shared__ float s_pimg[P_][T_];      // softmax over t, per row p
    __shared__ float s_ptit[T_][P_];      // softmax over p, per row t
    __shared__ float s_mask[T_];

    int tid = threadIdx.x;

    for (int i = tid; i < P_ * DH_; i += 256) {
        int p = i / DH_, d = i % DH_;
        s_img[p][d] = imgp[(size_t)p * D_ + d];
    }
    for (int i = tid; i < T_ * DH_; i += 256) {
        int t = i / DH_, d = i % DH_;
        s_tit[t][d] = titp[(size_t)t * D_ + d];
    }
    if (tid < T_) s_mask[tid] = (float)mp[tid];
    __syncthreads();

    // raw[p][t] = (img_p . tit_t) / sqrt(64)
    for (int i = tid; i < P_ * T_; i += 256) {
        int p = i / T_, t = i % T_;
        float acc = 0.f;
        #pragma unroll
        for (int d = 0; d < DH_; d++) acc += s_img[p][d] * s_tit[t][d];
        s_raw[p][t] = acc * 0.125f;
    }
    __syncthreads();

    // p_img: row p, scale_img[h,p], mask on t, softmax over t
    if (tid < P_) {
        int p = tid;
        float sc = scale_img[h * P_ + p];
        float row[T_];
        float mx = -INFINITY;
        #pragma unroll
        for (int t = 0; t < T_; t++) {
            float v = (s_mask[t] != 0.f) ? s_raw[p][t] * sc : NEGV;
            row[t] = v;
            mx = fmaxf(mx, v);
        }
        float sum = 0.f;
        #pragma unroll
        for (int t = 0; t < T_; t++) { float e = expf(row[t] - mx); row[t] = e; sum += e; }
        float inv = 1.f / sum;
        #pragma unroll
        for (int t = 0; t < T_; t++) s_pimg[p][t] = row[t] * inv;
    }
    // p_tit: row t, scale_title[h,t], whole row NEG if mask[t]==0 (-> uniform), softmax over p
    if (tid >= 64 && tid < 64 + T_) {
        int t = tid - 64;
        float sc = scale_title[h * T_ + t];
        bool dead = (s_mask[t] == 0.f);
        float mx = -INFINITY;
        for (int p = 0; p < P_; p++) {
            float v = dead ? NEGV : s_raw[p][t] * sc;
            mx = fmaxf(mx, v);
        }
        float sum = 0.f;
        for (int p = 0; p < P_; p++) {
            float v = dead ? NEGV : s_raw[p][t] * sc;
            float e = expf(v - mx);
            s_ptit[t][p] = e;
            sum += e;
        }
        float inv = 1.f / sum;
        for (int p = 0; p < P_; p++) s_ptit[t][p] *= inv;
    }
    __syncthreads();

    // attn_img[t,d] = sum_p p_tit[t,p] * img[p,d]   (title-side tokens)
    float* out_img = attn + (size_t)bl * T_ * D_ + h * DH_;
    for (int i = tid; i < T_ * DH_; i += 256) {
        int t = i / DH_, d = i % DH_;
        float acc = 0.f;
        #pragma unroll 7
        for (int p = 0; p < P_; p++) acc += s_ptit[t][p] * s_img[p][d];
        out_img[(size_t)t * D_ + d] = acc;
    }
    // attn_tit[p,d] = sum_t p_img[p,t] * tit[t,d]   (img-side tokens)
    float* out_tit = attn + (size_t)IMG_TOK * D_ + (size_t)bl * P_ * D_ + h * DH_;
    for (int i = tid; i < P_ * DH_; i += 256) {
        int p = i / DH_, d = i % DH_;
        float acc = 0.f;
        #pragma unroll
        for (int t = 0; t < T_; t++) acc += s_pimg[p][t] * s_tit[t][d];
        out_tit[(size_t)p * D_ + d] = acc;
    }
}

// ---------------- GEMM: C[M,N] = A[M,K] @ W[N,K]^T + bias, optional tanh-GELU ----------------
__device__ __forceinline__ float gelu_t(float x) {
    float x3 = x * x * x;
    float u = 0.7978845608028654f * (x + 0.044715f * x3);
    return 0.5f * x * (1.f + tanhf(u));
}

__global__ void __launch_bounds__(256) gemm_kernel(
    const float* __restrict__ A, const float* __restrict__ W,
    const float* __restrict__ bias, float* __restrict__ C,
    int M, int N, int K, int act)
{
    __shared__ float As[16][68];
    __shared__ float Bs[16][68];

    int tid = threadIdx.x;
    int m0 = blockIdx.y * 64, n0 = blockIdx.x * 64;
    int lr = tid >> 2;           // 0..63 : tile row for loads
    int lk = (tid & 3) << 2;     // 0,4,8,12 : k offset for loads
    int ty = tid >> 4, tx = tid & 15;

    float acc[4][4];
    #pragma unroll
    for (int i = 0; i < 4; i++)
        #pragma unroll
        for (int j = 0; j < 4; j++) acc[i][j] = 0.f;

    const float* Aptr = A + (size_t)(m0 + lr) * K + lk;
    const float* Wptr = W + (size_t)(n0 + lr) * K + lk;
    bool arow_ok = (m0 + lr) < M;   // N,K always tile-divisible; only M needs guarding

    for (int k0 = 0; k0 < K; k0 += 16) {
        float4 av = arow_ok ? *(const float4*)(Aptr + k0) : make_float4(0.f, 0.f, 0.f, 0.f);
        float4 bv = *(const float4*)(Wptr + k0);
        As[lk + 0][lr] = av.x; As[lk + 1][lr] = av.y; As[lk + 2][lr] = av.z; As[lk + 3][lr] = av.w;
        Bs[lk + 0][lr] = bv.x; Bs[lk + 1][lr] = bv.y; Bs[lk + 2][lr] = bv.z; Bs[lk + 3][lr] = bv.w;
        __syncthreads();
        #pragma unroll
        for (int k = 0; k < 16; k++) {
            float4 a = *(const float4*)&As[k][ty << 2];
            float4 b = *(const float4*)&Bs[k][tx << 2];
            acc[0][0] += a.x * b.x; acc[0][1] += a.x * b.y; acc[0][2] += a.x * b.z; acc[0][3] += a.x * b.w;
            acc[1][0] += a.y * b.x; acc[1][1] += a.y * b.y; acc[1][2] += a.y * b.z; acc[1][3] += a.y * b.w;
            acc[2][0] += a.z * b.x; acc[2][1] += a.z * b.y; acc[2][2] += a.z * b.z; acc[2][3] += a.z * b.w;
            acc[3][0] += a.w * b.x; acc[3][1] += a.w * b.y; acc[3][2] += a.w * b.z; acc[3][3] += a.w * b.w;
        }
        __syncthreads();
    }

    float4 bias4 = *(const float4*)(bias + n0 + (tx << 2));
    #pragma unroll
    for (int i = 0; i < 4; i++) {
        int row = m0 + (ty << 2) + i;
        if (row >= M) continue;
        float4 v;
        v.x = acc[i][0] + bias4.x;
        v.y = acc[i][1] + bias4.y;
        v.z = acc[i][2] + bias4.z;
        v.w = acc[i][3] + bias4.w;
        if (act) { v.x = gelu_t(v.x); v.y = gelu_t(v.y); v.z = gelu_t(v.z); v.w = gelu_t(v.w); }
        *(float4*)(C + (size_t)row * N + n0 + (tx << 2)) = v;
    }
}

// ---------------- residual + LayerNorm (ddof=1, a*(x-mean)/(std+eps)+b), one warp per token ----------------
__global__ void ln_res_kernel(
    const float* __restrict__ hid, const float* __restrict__ ffn,
    const float* __restrict__ aimg, const float* __restrict__ bimg,
    const float* __restrict__ atit, const float* __restrict__ btit,
    float* __restrict__ out)
{
    int tok = blockIdx.x;
    const float* a  = (tok < IMG_TOK) ? aimg : atit;
    const float* bb = (tok < IMG_TOK) ? bimg : btit;
    const float* x  = ffn + (size_t)tok * D_;
    const float* hh = hid + (size_t)tok * D_;
    float* o        = out + (size_t)tok * D_;

    int lane = threadIdx.x;   // 32 threads
    float v[16];
    float s = 0.f;
    #pragma unroll
    for (int i = 0; i < 4; i++) {
        float4 t4 = *(const float4*)(x + lane * 4 + i * 128);
        v[i * 4 + 0] = t4.x; v[i * 4 + 1] = t4.y; v[i * 4 + 2] = t4.z; v[i * 4 + 3] = t4.w;
        s += t4.x + t4.y + t4.z + t4.w;
    }
    #pragma unroll
    for (int off = 16; off > 0; off >>= 1) s += __shfl_xor_sync(0xffffffffu, s, off);
    float mean = s * (1.f / 512.f);

    float sq = 0.f;
    #pragma unroll
    for (int i = 0; i < 16; i++) { float d = v[i] - mean; sq += d * d; }
    #pragma unroll
    for (int off = 16; off > 0; off >>= 1) sq += __shfl_xor_sync(0xffffffffu, sq, off);
    float stdv = sqrtf(sq * (1.f / 511.f));   // ddof = 1
    float inv = 1.f / (stdv + EPS_);

    #pragma unroll
    for (int i = 0; i < 4; i++) {
        int c0 = lane * 4 + i * 128;
        float4 a4  = *(const float4*)(a  + c0);
        float4 b4  = *(const float4*)(bb + c0);
        float4 h4  = *(const float4*)(hh + c0);
        float4 r;
        r.x = h4.x + a4.x * (v[i * 4 + 0] - mean) * inv + b4.x;
        r.y = h4.y + a4.y * (v[i * 4 + 1] - mean) * inv + b4.y;
        r.z = h4.z + a4.z * (v[i * 4 + 2] - mean) * inv + b4.z;
        r.w = h4.w + a4.w * (v[i * 4 + 3] - mean) * inv + b4.w;
        *(float4*)(o + c0) = r;
    }
}

// ---------------- launch ----------------
extern "C" void kernel_launch(void* const* d_in, const int* in_sizes, int n_in,
                              void* d_out, int out_size)
{
    const float* img         = (const float*)d_in[0];
    const float* title       = (const float*)d_in[1];
    const int*   mask        = (const int*)  d_in[2];
    const float* scale_img   = (const float*)d_in[3];
    const float* scale_title = (const float*)d_in[4];
    const float* w_proj      = (const float*)d_in[5];
    const float* b_proj      = (const float*)d_in[6];
    const float* w1_img      = (const float*)d_in[7];
    const float* b1_img      = (const float*)d_in[8];
    const float* w2_img      = (const float*)d_in[9];
    const float* b2_img      = (const float*)d_in[10];
    const float* w1_tit      = (const float*)d_in[11];
    const float* b1_tit      = (const float*)d_in[12];
    const float* w2_tit      = (const float*)d_in[13];
    const float* b2_tit      = (const float*)d_in[14];
    const float* ln_a_img    = (const float*)d_in[15];
    const float* ln_b_img    = (const float*)d_in[16];
    const float* ln_a_tit    = (const float*)d_in[17];
    const float* ln_b_tit    = (const float*)d_in[18];
    float* out = (float*)d_out;

    float *attn, *hid, *ffn1, *ffn2;
    cudaGetSymbolAddress((void**)&attn, g_attn);
    cudaGetSymbolAddress((void**)&hid,  g_hid);
    cudaGetSymbolAddress((void**)&ffn1, g_ffn1);
    cudaGetSymbolAddress((void**)&ffn2, g_ffn2);

    // 1) attention: scores + dual softmax + both weighted sums
    attn_kernel<<<B_ * L_ * H_, 256>>>(img, title, mask, scale_img, scale_title, attn);

    // 2) shared projection for both token sets in one GEMM (they share w_proj)
    gemm_kernel<<<dim3(D_ / 64, (NTOK + 63) / 64), 256>>>(attn, w_proj, b_proj, hid, NTOK, D_, D_, 0);

    // 3) FFN1 (+GELU), per branch
    gemm_kernel<<<dim3(DFF_ / 64, (IMG_TOK + 63) / 64), 256>>>(
        hid, w1_img, b1_img, ffn1, IMG_TOK, DFF_, D_, 1);
    gemm_kernel<<<dim3(DFF_ / 64, (TIT_TOK + 63) / 64), 256>>>(
        hid + (size_t)IMG_TOK * D_, w1_tit, b1_tit,
        ffn1 + (size_t)IMG_TOK * DFF_, TIT_TOK, DFF_, D_, 1);

    // 4) FFN2, per branch
    gemm_kernel<<<dim3(D_ / 64, (IMG_TOK + 63) / 64), 256>>>(
        ffn1, w2_img, b2_img, ffn2, IMG_TOK, D_, DFF_, 0);
    gemm_kernel<<<dim3(D_ / 64, (TIT_TOK + 63) / 64), 256>>>(
        ffn1 + (size_t)IMG_TOK * DFF_, w2_tit, b2_tit,
        ffn2 + (size_t)IMG_TOK * D_, TIT_TOK, D_, DFF_, 0);

    // 5) out = hid + LN(ffn2)  -> d_out (img tokens first, then tit tokens)
    ln_res_kernel<<<NTOK, 32>>>(hid, ffn2, ln_a_img, ln_b_img, ln_a_tit, ln_b_tit, out);
}

// round 4
// speedup vs baseline: 1.9101x; 1.9101x over previous
#include <cuda_runtime.h>
#include <math.h>
#include <stdint.h>

// Problem constants
#define B_   16
#define L_   50
#define P_   49
#define T_   20
#define D_   512
#define H_   8
#define DH_  64
#define DFF_ 2048
#define IMG_TOK (B_*L_*T_)   // 16000
#define TIT_TOK (B_*L_*P_)   // 39200
#define NTOK (IMG_TOK + TIT_TOK)  // 55200
#define NEGV (-1000000000.0f)
#define EPS_ 1e-6f

// ---------------- scratch ----------------
__device__ float g_attn[NTOK * D_];
__device__ float g_hid [NTOK * D_];
__device__ float g_ffn1[(size_t)NTOK * DFF_];
__device__ float g_ffn2[NTOK * D_];

__device__ __forceinline__ uint32_t f2tf32(float f) {
    uint32_t r; asm("cvt.rna.tf32.f32 %0, %1;" : "=r"(r) : "f"(f)); return r;
}
__device__ __forceinline__ float gelu_t(float x) {
    float x3 = x * x * x;
    float u = 0.7978845608028654f * (x + 0.044715f * x3);
    return 0.5f * x * (1.f + tanhf(u));
}
__device__ __forceinline__ void mma_tf32(float* c, const uint32_t* a, const uint32_t* b) {
    asm volatile(
        "mma.sync.aligned.m16n8k8.row.col.f32.tf32.tf32.f32 "
        "{%0,%1,%2,%3}, {%4,%5,%6,%7}, {%8,%9}, {%0,%1,%2,%3};"
        : "+f"(c[0]), "+f"(c[1]), "+f"(c[2]), "+f"(c[3])
        : "r"(a[0]), "r"(a[1]), "r"(a[2]), "r"(a[3]), "r"(b[0]), "r"(b[1]));
}

// ---------------- tensor-core GEMM via mma.sync (tf32) ----------------
// C[M,N] = A[M,K] @ W[N,K]^T + bias (+GELU). Tile 128x128, K-chunk 32.
// Double-buffered SMEM + register prefetch. 256 threads = 8 warps (4 m x 2 n).
#define SROW 36                    // smem row stride (floats): 16B-aligned, conflict-free
#define TILE_U32 (128 * SROW)      // 4608 u32 per tile
#define MM_SMEM (4 * TILE_U32 * 4) // 73728 bytes

__global__ void __launch_bounds__(256) mma_gemm(
    const float* __restrict__ A, const float* __restrict__ W,
    const float* __restrict__ bias, float* __restrict__ C,
    int M, int N, int K, int act)
{
    extern __shared__ uint32_t sh[];
    uint32_t* sA[2] = { sh,                sh + TILE_U32 };
    uint32_t* sB[2] = { sh + 2 * TILE_U32, sh + 3 * TILE_U32 };

    const int tid = threadIdx.x;
    const int m0 = blockIdx.y * 128, n0 = blockIdx.x * 128;

    const int w = tid >> 5, lane = tid & 31;
    const int wm = w & 3, wn = w >> 2;          // warp tile: rows wm*32, cols wn*64
    const int group = lane >> 2, quad = lane & 3;

    // gmem load mapping: idx = tid + t*256 -> row = idx>>3 (0..127), c4 = idx&7 (float4 col)
    const int lrow0 = tid >> 3;        // rows lrow0 + t*32
    const int lc4   = tid & 7;

    float acc[2][8][4];
    #pragma unroll
    for (int i = 0; i < 2; i++)
        #pragma unroll
        for (int j = 0; j < 8; j++)
            #pragma unroll
            for (int q = 0; q < 4; q++) acc[i][j][q] = 0.f;

    const int nch = K >> 5;
    float4 pa[4], pw[4];

    auto ldg_chunk = [&](int kc) {
        #pragma unroll
        for (int t = 0; t < 4; t++) {
            int row = lrow0 + t * 32;
            pa[t] = (m0 + row < M) ? *(const float4*)(A + (size_t)(m0 + row) * K + kc + lc4 * 4)
                                   : make_float4(0.f, 0.f, 0.f, 0.f);
            pw[t] = *(const float4*)(W + (size_t)(n0 + row) * K + kc + lc4 * 4);
        }
    };
    auto sts_chunk = [&](int buf) {
        uint32_t* ap = sA[buf];
        uint32_t* wp = sB[buf];
        #pragma unroll
        for (int t = 0; t < 4; t++) {
            int row = lrow0 + t * 32;
            uint4 at; at.x = f2tf32(pa[t].x); at.y = f2tf32(pa[t].y);
                      at.z = f2tf32(pa[t].z); at.w = f2tf32(pa[t].w);
            *(uint4*)(ap + row * SROW + lc4 * 4) = at;
            uint4 wt; wt.x = f2tf32(pw[t].x); wt.y = f2tf32(pw[t].y);
                      wt.z = f2tf32(pw[t].z); wt.w = f2tf32(pw[t].w);
            *(uint4*)(wp + row * SROW + lc4 * 4) = wt;
        }
    };
    auto compute = [&](int buf) {
        const uint32_t* ap = sA[buf];
        const uint32_t* bp = sB[buf];
        #pragma unroll
        for (int ks = 0; ks < 4; ks++) {
            const int k0 = ks * 8;
            uint32_t afr[2][4];
            #pragma unroll
            for (int mi = 0; mi < 2; mi++) {
                int r = wm * 32 + mi * 16 + group;
                afr[mi][0] = ap[(r    ) * SROW + k0 + quad];
                afr[mi][1] = ap[(r + 8) * SROW + k0 + quad];
                afr[mi][2] = ap[(r    ) * SROW + k0 + quad + 4];
                afr[mi][3] = ap[(r + 8) * SROW + k0 + quad + 4];
            }
            uint32_t bfr[8][2];
            #pragma unroll
            for (int ni = 0; ni < 8; ni++) {
                int n = wn * 64 + ni * 8 + group;
                bfr[ni][0] = bp[n * SROW + k0 + quad];
                bfr[ni][1] = bp[n * SROW + k0 + quad + 4];
            }
            #pragma unroll
            for (int mi = 0; mi < 2; mi++)
                #pragma unroll
                for (int ni = 0; ni < 8; ni++)
                    mma_tf32(acc[mi][ni], afr[mi], bfr[ni]);
        }
    };

    // prologue
    ldg_chunk(0);
    sts_chunk(0);
    __syncthreads();

    for (int c = 0; c < nch; c++) {
        int cur = c & 1;
        bool more = (c + 1 < nch);
        if (more) ldg_chunk((c + 1) << 5);   // issue LDGs; latency hidden by compute
        compute(cur);
        __syncthreads();                     // all warps done reading buf[cur]
        if (more) {
            sts_chunk(cur ^ 1);              // waits on LDG data here
            __syncthreads();
        }
    }

    // epilogue: bias + optional GELU, write fp32
    #pragma unroll
    for (int ni = 0; ni < 8; ni++) {
        int cc = n0 + wn * 64 + ni * 8 + quad * 2;
        float2 b2 = *(const float2*)(bias + cc);
        #pragma unroll
        for (int mi = 0; mi < 2; mi++) {
            int r = m0 + wm * 32 + mi * 16 + group;
            if (r < M) {
                float2 v0;
                v0.x = acc[mi][ni][0] + b2.x;
                v0.y = acc[mi][ni][1] + b2.y;
                if (act) { v0.x = gelu_t(v0.x); v0.y = gelu_t(v0.y); }
                *(float2*)(C + (size_t)r * N + cc) = v0;
            }
            if (r + 8 < M) {
                float2 v1;
                v1.x = acc[mi][ni][2] + b2.x;
                v1.y = acc[mi][ni][3] + b2.y;
                if (act) { v1.x = gelu_t(v1.x); v1.y = gelu_t(v1.y); }
                *(float2*)(C + (size_t)(r + 8) * N + cc) = v1;
            }
        }
    }
}

// ---------------- attention kernel (fp32) ----------------
__global__ void __launch_bounds__(256) attn_kernel(
    const float* __restrict__ img, const float* __restrict__ title,
    const int* __restrict__ mask,
    const float* __restrict__ scale_img, const float* __restrict__ scale_title,
    float* __restrict__ attn)
{
    int blk = blockIdx.x;
    int h  = blk % H_;
    int bl = blk / H_;

    const float* imgp = img   + (size_t)bl * P_ * D_ + h * DH_;
    const float* titp = title + (size_t)bl * T_ * D_ + h * DH_;
    const int*   mp   = mask  + bl * T_;

    __shared__ float s_img[P_][DH_ + 1];
    __shared__ float s_tit[T_][DH_ + 1];
    __shared__ float s_raw [P_][T_];
    __shared__ float s_pimg[P_][T_];
    __shared__ float s_ptit[T_][P_];
    __shared__ float s_mask[T_];

    int tid = threadIdx.x;

    for (int i = tid; i < P_ * DH_; i += 256) {
        int p = i / DH_, d = i % DH_;
        s_img[p][d] = imgp[(size_t)p * D_ + d];
    }
    for (int i = tid; i < T_ * DH_; i += 256) {
        int t = i / DH_, d = i % DH_;
        s_tit[t][d] = titp[(size_t)t * D_ + d];
    }
    if (tid < T_) s_mask[tid] = (float)mp[tid];
    __syncthreads();

    for (int i = tid; i < P_ * T_; i += 256) {
        int p = i / T_, t = i % T_;
        float acc = 0.f;
        #pragma unroll
        for (int d = 0; d < DH_; d++) acc += s_img[p][d] * s_tit[t][d];
        s_raw[p][t] = acc * 0.125f;
    }
    __syncthreads();

    if (tid < P_) {
        int p = tid;
        float sc = scale_img[h * P_ + p];
        float row[T_];
        float mx = -INFINITY;
        #pragma unroll
        for (int t = 0; t < T_; t++) {
            float v = (s_mask[t] != 0.f) ? s_raw[p][t] * sc : NEGV;
            row[t] = v;
            mx = fmaxf(mx, v);
        }
        float sum = 0.f;
        #pragma unroll
        for (int t = 0; t < T_; t++) { float e = expf(row[t] - mx); row[t] = e; sum += e; }
        float inv = 1.f / sum;
        #pragma unroll
        for (int t = 0; t < T_; t++) s_pimg[p][t] = row[t] * inv;
    }
    if (tid >= 64 && tid < 64 + T_) {
        int t = tid - 64;
        float sc = scale_title[h * T_ + t];
        bool dead = (s_mask[t] == 0.f);
        float mx = -INFINITY;
        for (int p = 0; p < P_; p++) {
            float v = dead ? NEGV : s_raw[p][t] * sc;
            mx = fmaxf(mx, v);
        }
        float sum = 0.f;
        for (int p = 0; p < P_; p++) {
            float v = dead ? NEGV : s_raw[p][t] * sc;
            float e = expf(v - mx);
            s_ptit[t][p] = e;
            sum += e;
        }
        float inv = 1.f / sum;
        for (int p = 0; p < P_; p++) s_ptit[t][p] *= inv;
    }
    __syncthreads();

    float* out_img = attn + (size_t)bl * T_ * D_ + h * DH_;
    for (int i = tid; i < T_ * DH_; i += 256) {
        int t = i / DH_, d = i % DH_;
        float acc = 0.f;
        #pragma unroll 7
        for (int p = 0; p < P_; p++) acc += s_ptit[t][p] * s_img[p][d];
        out_img[(size_t)t * D_ + d] = acc;
    }
    float* out_tit = attn + (size_t)IMG_TOK * D_ + (size_t)bl * P_ * D_ + h * DH_;
    for (int i = tid; i < P_ * DH_; i += 256) {
        int p = i / DH_, d = i % DH_;
        float acc = 0.f;
        #pragma unroll
        for (int t = 0; t < T_; t++) acc += s_pimg[p][t] * s_tit[t][d];
        out_tit[(size_t)p * D_ + d] = acc;
    }
}

// ---------------- residual + LayerNorm ----------------
__global__ void ln_res_kernel(
    const float* __restrict__ hid, const float* __restrict__ ffn,
    const float* __restrict__ aimg, const float* __restrict__ bimg,
    const float* __restrict__ atit, const float* __restrict__ btit,
    float* __restrict__ out)
{
    int tok = blockIdx.x;
    const float* a  = (tok < IMG_TOK) ? aimg : atit;
    const float* bb = (tok < IMG_TOK) ? bimg : btit;
    const float* x  = ffn + (size_t)tok * D_;
    const float* hh = hid + (size_t)tok * D_;
    float* o        = out + (size_t)tok * D_;

    int lane = threadIdx.x;
    float v[16];
    float s = 0.f;
    #pragma unroll
    for (int i = 0; i < 4; i++) {
        float4 t4 = *(const float4*)(x + lane * 4 + i * 128);
        v[i*4+0] = t4.x; v[i*4+1] = t4.y; v[i*4+2] = t4.z; v[i*4+3] = t4.w;
        s += t4.x + t4.y + t4.z + t4.w;
    }
    #pragma unroll
    for (int off = 16; off > 0; off >>= 1) s += __shfl_xor_sync(0xffffffffu, s, off);
    float mean = s * (1.f / 512.f);

    float sq = 0.f;
    #pragma unroll
    for (int i = 0; i < 16; i++) { float d = v[i] - mean; sq += d * d; }
    #pragma unroll
    for (int off = 16; off > 0; off >>= 1) sq += __shfl_xor_sync(0xffffffffu, sq, off);
    float stdv = sqrtf(sq * (1.f / 511.f));
    float inv = 1.f / (stdv + EPS_);

    #pragma unroll
    for (int i = 0; i < 4; i++) {
        int c0 = lane * 4 + i * 128;
        float4 a4 = *(const float4*)(a  + c0);
        float4 b4 = *(const float4*)(bb + c0);
        float4 h4 = *(const float4*)(hh + c0);
        float4 r;
        r.x = h4.x + a4.x * (v[i*4+0] - mean) * inv + b4.x;
        r.y = h4.y + a4.y * (v[i*4+1] - mean) * inv + b4.y;
        r.z = h4.z + a4.z * (v[i*4+2] - mean) * inv + b4.z;
        r.w = h4.w + a4.w * (v[i*4+3] - mean) * inv + b4.w;
        *(float4*)(o + c0) = r;
    }
}

// ---------------- launch ----------------
extern "C" void kernel_launch(void* const* d_in, const int* in_sizes, int n_in,
                              void* d_out, int out_size)
{
    const float* img         = (const float*)d_in[0];
    const float* title       = (const float*)d_in[1];
    const int*   mask        = (const int*)  d_in[2];
    const float* scale_img   = (const float*)d_in[3];
    const float* scale_title = (const float*)d_in[4];
    const float* w_proj      = (const float*)d_in[5];
    const float* b_proj      = (const float*)d_in[6];
    const float* w1_img      = (const float*)d_in[7];
    const float* b1_img      = (const float*)d_in[8];
    const float* w2_img      = (const float*)d_in[9];
    const float* b2_img      = (const float*)d_in[10];
    const float* w1_tit      = (const float*)d_in[11];
    const float* b1_tit      = (const float*)d_in[12];
    const float* w2_tit      = (const float*)d_in[13];
    const float* b2_tit      = (const float*)d_in[14];
    const float* ln_a_img    = (const float*)d_in[15];
    const float* ln_b_img    = (const float*)d_in[16];
    const float* ln_a_tit    = (const float*)d_in[17];
    const float* ln_b_tit    = (const float*)d_in[18];
    float* out = (float*)d_out;

    float *attn, *hid, *ffn1, *ffn2;
    cudaGetSymbolAddress((void**)&attn, g_attn);
    cudaGetSymbolAddress((void**)&hid,  g_hid);
    cudaGetSymbolAddress((void**)&ffn1, g_ffn1);
    cudaGetSymbolAddress((void**)&ffn2, g_ffn2);

    cudaFuncSetAttribute(mma_gemm, cudaFuncAttributeMaxDynamicSharedMemorySize, MM_SMEM);

    // 1) attention
    attn_kernel<<<B_ * L_ * H_, 256>>>(img, title, mask, scale_img, scale_title, attn);

    // 2) shared projection (both token sets, one GEMM)
    mma_gemm<<<dim3(D_ / 128, (NTOK + 127) / 128), 256, MM_SMEM>>>(
        attn, w_proj, b_proj, hid, NTOK, D_, D_, 0);

    // 3) FFN1 (+GELU) per branch
    mma_gemm<<<dim3(DFF_ / 128, (IMG_TOK + 127) / 128), 256, MM_SMEM>>>(
        hid, w1_img, b1_img, ffn1, IMG_TOK, DFF_, D_, 1);
    mma_gemm<<<dim3(DFF_ / 128, (TIT_TOK + 127) / 128), 256, MM_SMEM>>>(
        hid + (size_t)IMG_TOK * D_, w1_tit, b1_tit,
        ffn1 + (size_t)IMG_TOK * DFF_, TIT_TOK, DFF_, D_, 1);

    // 4) FFN2 per branch
    mma_gemm<<<dim3(D_ / 128, (IMG_TOK + 127) / 128), 256, MM_SMEM>>>(
        ffn1, w2_img, b2_img, ffn2, IMG_TOK, D_, DFF_, 0);
    mma_gemm<<<dim3(D_ / 128, (TIT_TOK + 127) / 128), 256, MM_SMEM>>>(
        ffn1 + (size_t)IMG_TOK * DFF_, w2_tit, b2_tit,
        ffn2 + (size_t)IMG_TOK * D_, TIT_TOK, D_, DFF_, 0);

    // 5) out = hid + LN(ffn2)
    ln_res_kernel<<<NTOK, 32>>>(hid, ffn2, ln_a_img, ln_b_img, ln_a_tit, ln_b_tit, out);
}

// round 5
// speedup vs baseline: 2.9561x; 1.5476x over previous
#include <cuda_runtime.h>
#include <math.h>
#include <stdint.h>

// Problem constants
#define B_   16
#define L_   50
#define P_   49
#define T_   20
#define D_   512
#define H_   8
#define DH_  64
#define DFF_ 2048
#define IMG_TOK (B_*L_*T_)   // 16000  (= 125 tiles of 128, exactly)
#define TIT_TOK (B_*L_*P_)   // 39200
#define NTOK (IMG_TOK + TIT_TOK)  // 55200
#define NEGV (-1000000000.0f)
#define EPS_ 1e-6f

// ---------------- scratch ----------------
__device__ float g_attn[NTOK * D_];
__device__ float g_hid [NTOK * D_];
__device__ float g_ffn1[(size_t)NTOK * DFF_];
__device__ float g_ffn2[NTOK * D_];

__device__ __forceinline__ uint32_t f2tf32(float f) {
    uint32_t r; asm("cvt.rna.tf32.f32 %0, %1;" : "=r"(r) : "f"(f)); return r;
}
__device__ __forceinline__ float gelu_t(float x) {
    float x3 = x * x * x;
    float u = 0.7978845608028654f * (x + 0.044715f * x3);
    return 0.5f * x * (1.f + tanhf(u));
}
__device__ __forceinline__ void mma_tf32(float* c, const uint32_t* a, const uint32_t* b) {
    asm volatile(
        "mma.sync.aligned.m16n8k8.row.col.f32.tf32.tf32.f32 "
        "{%0,%1,%2,%3}, {%4,%5,%6,%7}, {%8,%9}, {%0,%1,%2,%3};"
        : "+f"(c[0]), "+f"(c[1]), "+f"(c[2]), "+f"(c[3])
        : "r"(a[0]), "r"(a[1]), "r"(a[2]), "r"(a[3]), "r"(b[0]), "r"(b[1]));
}
__device__ __forceinline__ void cp_async16(uint32_t dst, const void* src, uint32_t nbytes) {
    asm volatile("cp.async.cg.shared.global [%0], [%1], 16, %2;"
                 :: "r"(dst), "l"(src), "r"(nbytes));
}
__device__ __forceinline__ void cp_commit() {
    asm volatile("cp.async.commit_group;" ::: "memory");
}
template <int N>
__device__ __forceinline__ void cp_wait() {
    asm volatile("cp.async.wait_group %0;" :: "n"(N) : "memory");
}

// ---------------- tensor-core GEMM via mma.sync tf32 + cp.async ----------------
// C[M,N] = A[M,K] @ Wsel[N,K]^T + bias (+GELU). Wsel = W0 for m-tiles < split, else W1.
// Tile 128x128, K-chunk 32, double-buffered cp.async, 256 threads = 8 warps (4m x 2n).
#define SROW 36                       // smem row stride (floats); row = 144 B
#define TILE_BYTES (128 * SROW * 4)   // 18432 B per matrix per buffer
#define MM_SMEM (4 * TILE_BYTES)      // 73728 B

__global__ void __launch_bounds__(256, 2) mma_gemm(
    const float* __restrict__ A,
    const float* __restrict__ W0, const float* __restrict__ b0,
    const float* __restrict__ W1, const float* __restrict__ b1,
    int split_tile,
    float* __restrict__ C, int M, int N, int K, int act)
{
    extern __shared__ float sh[];
    const uint32_t sm_base = (uint32_t)__cvta_generic_to_shared(sh);
    const uint32_t aU[2] = { sm_base,                  sm_base + TILE_BYTES };
    const uint32_t bU[2] = { sm_base + 2 * TILE_BYTES, sm_base + 3 * TILE_BYTES };
    const float* aF[2] = { sh,                      sh + TILE_BYTES / 4 };
    const float* bF[2] = { sh + 2 * TILE_BYTES / 4, sh + 3 * TILE_BYTES / 4 };

    const int tid = threadIdx.x;
    const int m0 = blockIdx.y * 128, n0 = blockIdx.x * 128;
    const float* W    = (blockIdx.y < split_tile) ? W0 : W1;
    const float* bias = (blockIdx.y < split_tile) ? b0 : b1;

    const int w = tid >> 5, lane = tid & 31;
    const int wm = w & 3, wn = w >> 2;          // warp tile: rows wm*32, cols wn*64
    const int group = lane >> 2, quad = lane & 3;

    const int lrow0 = tid >> 3;        // copy mapping: rows lrow0 + t*32
    const int lc4   = tid & 7;         // 16B column

    float acc[2][8][4];
    #pragma unroll
    for (int i = 0; i < 2; i++)
        #pragma unroll
        for (int j = 0; j < 8; j++)
            #pragma unroll
            for (int q = 0; q < 4; q++) acc[i][j][q] = 0.f;

    const int nch = K >> 5;

    auto issue = [&](int buf, int kc) {
        #pragma unroll
        for (int t = 0; t < 4; t++) {
            int row = lrow0 + t * 32;
            uint32_t off = (uint32_t)(row * 144 + lc4 * 16);
            size_t arow = (m0 + row < M) ? (size_t)(m0 + row) : 0;
            cp_async16(aU[buf] + off, A + arow * K + kc + lc4 * 4,
                       (m0 + row < M) ? 16u : 0u);
            cp_async16(bU[buf] + off, W + (size_t)(n0 + row) * K + kc + lc4 * 4, 16u);
        }
        cp_commit();
    };

    auto compute = [&](int buf) {
        const float* ap = aF[buf];
        const float* bp = bF[buf];
        #pragma unroll
        for (int ks = 0; ks < 4; ks++) {
            const int k0 = ks * 8;
            uint32_t afr[2][4];
            #pragma unroll
            for (int mi = 0; mi < 2; mi++) {
                int r = wm * 32 + mi * 16 + group;
                afr[mi][0] = f2tf32(ap[(r    ) * SROW + k0 + quad]);
                afr[mi][1] = f2tf32(ap[(r + 8) * SROW + k0 + quad]);
                afr[mi][2] = f2tf32(ap[(r    ) * SROW + k0 + quad + 4]);
                afr[mi][3] = f2tf32(ap[(r + 8) * SROW + k0 + quad + 4]);
            }
            uint32_t bfr[8][2];
            #pragma unroll
            for (int ni = 0; ni < 8; ni++) {
                int n = wn * 64 + ni * 8 + group;
                bfr[ni][0] = f2tf32(bp[n * SROW + k0 + quad]);
                bfr[ni][1] = f2tf32(bp[n * SROW + k0 + quad + 4]);
            }
            #pragma unroll
            for (int mi = 0; mi < 2; mi++)
                #pragma unroll
                for (int ni = 0; ni < 8; ni++)
                    mma_tf32(acc[mi][ni], afr[mi], bfr[ni]);
        }
    };

    // prologue
    issue(0, 0);

    for (int c = 0; c < nch; c++) {
        int cur = c & 1;
        if (c + 1 < nch) {
            issue(cur ^ 1, (c + 1) << 5);
            cp_wait<1>();            // chunk c landed; chunk c+1 still in flight
        } else {
            cp_wait<0>();
        }
        __syncthreads();
        compute(cur);
        __syncthreads();             // all warps done with buf[cur] before c+2 overwrites
    }

    // epilogue: bias + optional GELU, write fp32
    #pragma unroll
    for (int ni = 0; ni < 8; ni++) {
        int cc = n0 + wn * 64 + ni * 8 + quad * 2;
        float2 b2 = *(const float2*)(bias + cc);
        #pragma unroll
        for (int mi = 0; mi < 2; mi++) {
            int r = m0 + wm * 32 + mi * 16 + group;
            if (r < M) {
                float2 v0;
                v0.x = acc[mi][ni][0] + b2.x;
                v0.y = acc[mi][ni][1] + b2.y;
                if (act) { v0.x = gelu_t(v0.x); v0.y = gelu_t(v0.y); }
                *(float2*)(C + (size_t)r * N + cc) = v0;
            }
            if (r + 8 < M) {
                float2 v1;
                v1.x = acc[mi][ni][2] + b2.x;
                v1.y = acc[mi][ni][3] + b2.y;
                if (act) { v1.x = gelu_t(v1.x); v1.y = gelu_t(v1.y); }
                *(float2*)(C + (size_t)(r + 8) * N + cc) = v1;
            }
        }
    }
}

// ---------------- attention kernel (fp32) ----------------
__global__ void __launch_bounds__(256) attn_kernel(
    const float* __restrict__ img, const float* __restrict__ title,
    const int* __restrict__ mask,
    const float* __restrict__ scale_img, const float* __restrict__ scale_title,
    float* __restrict__ attn)
{
    int blk = blockIdx.x;
    int h  = blk % H_;
    int bl = blk / H_;

    const float* imgp = img   + (size_t)bl * P_ * D_ + h * DH_;
    const float* titp = title + (size_t)bl * T_ * D_ + h * DH_;
    const int*   mp   = mask  + bl * T_;

    __shared__ float s_img[P_][DH_ + 1];
    __shared__ float s_tit[T_][DH_ + 1];
    __shared__ float s_raw [P_][T_];
    __shared__ float s_pimg[P_][T_];
    __shared__ float s_ptit[T_][P_];
    __shared__ float s_mask[T_];

    int tid = threadIdx.x;

    for (int i = tid; i < P_ * DH_; i += 256) {
        int p = i / DH_, d = i % DH_;
        s_img[p][d] = imgp[(size_t)p * D_ + d];
    }
    for (int i = tid; i < T_ * DH_; i += 256) {
        int t = i / DH_, d = i % DH_;
        s_tit[t][d] = titp[(size_t)t * D_ + d];
    }
    if (tid < T_) s_mask[tid] = (float)mp[tid];
    __syncthreads();

    for (int i = tid; i < P_ * T_; i += 256) {
        int p = i / T_, t = i % T_;
        float acc = 0.f;
        #pragma unroll
        for (int d = 0; d < DH_; d++) acc += s_img[p][d] * s_tit[t][d];
        s_raw[p][t] = acc * 0.125f;
    }
    __syncthreads();

    if (tid < P_) {
        int p = tid;
        float sc = scale_img[h * P_ + p];
        float row[T_];
        float mx = -INFINITY;
        #pragma unroll
        for (int t = 0; t < T_; t++) {
            float v = (s_mask[t] != 0.f) ? s_raw[p][t] * sc : NEGV;
            row[t] = v;
            mx = fmaxf(mx, v);
        }
        float sum = 0.f;
        #pragma unroll
        for (int t = 0; t < T_; t++) { float e = expf(row[t] - mx); row[t] = e; sum += e; }
        float inv = 1.f / sum;
        #pragma unroll
        for (int t = 0; t < T_; t++) s_pimg[p][t] = row[t] * inv;
    }
    if (tid >= 64 && tid < 64 + T_) {
        int t = tid - 64;
        float sc = scale_title[h * T_ + t];
        bool dead = (s_mask[t] == 0.f);
        float mx = -INFINITY;
        for (int p = 0; p < P_; p++) {
            float v = dead ? NEGV : s_raw[p][t] * sc;
            mx = fmaxf(mx, v);
        }
        float sum = 0.f;
        for (int p = 0; p < P_; p++) {
            float v = dead ? NEGV : s_raw[p][t] * sc;
            float e = expf(v - mx);
            s_ptit[t][p] = e;
            sum += e;
        }
        float inv = 1.f / sum;
        for (int p = 0; p < P_; p++) s_ptit[t][p] *= inv;
    }
    __syncthreads();

    float* out_img = attn + (size_t)bl * T_ * D_ + h * DH_;
    for (int i = tid; i < T_ * DH_; i += 256) {
        int t = i / DH_, d = i % DH_;
        float acc = 0.f;
        #pragma unroll 7
        for (int p = 0; p < P_; p++) acc += s_ptit[t][p] * s_img[p][d];
        out_img[(size_t)t * D_ + d] = acc;
    }
    float* out_tit = attn + (size_t)IMG_TOK * D_ + (size_t)bl * P_ * D_ + h * DH_;
    for (int i = tid; i < P_ * DH_; i += 256) {
        int p = i / DH_, d = i % DH_;
        float acc = 0.f;
        #pragma unroll
        for (int t = 0; t < T_; t++) acc += s_pimg[p][t] * s_tit[t][d];
        out_tit[(size_t)p * D_ + d] = acc;
    }
}

// ---------------- residual + LayerNorm: 4 warps/block, one token per warp ----------------
__global__ void __launch_bounds__(128) ln_res_kernel(
    const float* __restrict__ hid, const float* __restrict__ ffn,
    const float* __restrict__ aimg, const float* __restrict__ bimg,
    const float* __restrict__ atit, const float* __restrict__ btit,
    float* __restrict__ out)
{
    int tok = blockIdx.x * 4 + (threadIdx.x >> 5);
    if (tok >= NTOK) return;
    const float* a  = (tok < IMG_TOK) ? aimg : atit;
    const float* bb = (tok < IMG_TOK) ? bimg : btit;
    const float* x  = ffn + (size_t)tok * D_;
    const float* hh = hid + (size_t)tok * D_;
    float* o        = out + (size_t)tok * D_;

    int lane = threadIdx.x & 31;
    float v[16];
    float s = 0.f;
    #pragma unroll
    for (int i = 0; i < 4; i++) {
        float4 t4 = *(const float4*)(x + lane * 4 + i * 128);
        v[i*4+0] = t4.x; v[i*4+1] = t4.y; v[i*4+2] = t4.z; v[i*4+3] = t4.w;
        s += t4.x + t4.y + t4.z + t4.w;
    }
    #pragma unroll
    for (int off = 16; off > 0; off >>= 1) s += __shfl_xor_sync(0xffffffffu, s, off);
    float mean = s * (1.f / 512.f);

    float sq = 0.f;
    #pragma unroll
    for (int i = 0; i < 16; i++) { float d = v[i] - mean; sq += d * d; }
    #pragma unroll
    for (int off = 16; off > 0; off >>= 1) sq += __shfl_xor_sync(0xffffffffu, sq, off);
    float stdv = sqrtf(sq * (1.f / 511.f));
    float inv = 1.f / (stdv + EPS_);

    #pragma unroll
    for (int i = 0; i < 4; i++) {
        int c0 = lane * 4 + i * 128;
        float4 a4 = *(const float4*)(a  + c0);
        float4 b4 = *(const float4*)(bb + c0);
        float4 h4 = *(const float4*)(hh + c0);
        float4 r;
        r.x = h4.x + a4.x * (v[i*4+0] - mean) * inv + b4.x;
        r.y = h4.y + a4.y * (v[i*4+1] - mean) * inv + b4.y;
        r.z = h4.z + a4.z * (v[i*4+2] - mean) * inv + b4.z;
        r.w = h4.w + a4.w * (v[i*4+3] - mean) * inv + b4.w;
        *(float4*)(o + c0) = r;
    }
}

// ---------------- launch ----------------
#define MTILES ((NTOK + 127) / 128)      // 432
#define SPLIT_TILE (IMG_TOK / 128)       // 125 (exact)

extern "C" void kernel_launch(void* const* d_in, const int* in_sizes, int n_in,
                              void* d_out, int out_size)
{
    const float* img         = (const float*)d_in[0];
    const float* title       = (const float*)d_in[1];
    const int*   mask        = (const int*)  d_in[2];
    const float* scale_img   = (const float*)d_in[3];
    const float* scale_title = (const float*)d_in[4];
    const float* w_proj      = (const float*)d_in[5];
    const float* b_proj      = (const float*)d_in[6];
    const float* w1_img      = (const float*)d_in[7];
    const float* b1_img      = (const float*)d_in[8];
    const float* w2_img      = (const float*)d_in[9];
    const float* b2_img      = (const float*)d_in[10];
    const float* w1_tit      = (const float*)d_in[11];
    const float* b1_tit      = (const float*)d_in[12];
    const float* w2_tit      = (const float*)d_in[13];
    const float* b2_tit      = (const float*)d_in[14];
    const float* ln_a_img    = (const float*)d_in[15];
    const float* ln_b_img    = (const float*)d_in[16];
    const float* ln_a_tit    = (const float*)d_in[17];
    const float* ln_b_tit    = (const float*)d_in[18];
    float* out = (float*)d_out;

    float *attn, *hid, *ffn1, *ffn2;
    cudaGetSymbolAddress((void**)&attn, g_attn);
    cudaGetSymbolAddress((void**)&hid,  g_hid);
    cudaGetSymbolAddress((void**)&ffn1, g_ffn1);
    cudaGetSymbolAddress((void**)&ffn2, g_ffn2);

    cudaFuncSetAttribute(mma_gemm, cudaFuncAttributeMaxDynamicSharedMemorySize, MM_SMEM);

    // 1) attention
    attn_kernel<<<B_ * L_ * H_, 256>>>(img, title, mask, scale_img, scale_title, attn);

    // 2) shared projection (all tokens, one weight)
    mma_gemm<<<dim3(D_ / 128, MTILES), 256, MM_SMEM>>>(
        attn, w_proj, b_proj, w_proj, b_proj, MTILES,
        hid, NTOK, D_, D_, 0);

    // 3) FFN1 (+GELU), both branches in one launch (split is tile-aligned)
    mma_gemm<<<dim3(DFF_ / 128, MTILES), 256, MM_SMEM>>>(
        hid, w1_img, b1_img, w1_tit, b1_tit, SPLIT_TILE,
        ffn1, NTOK, DFF_, D_, 1);

    // 4) FFN2, both branches in one launch
    mma_gemm<<<dim3(D_ / 128, MTILES), 256, MM_SMEM>>>(
        ffn1, w2_img, b2_img, w2_tit, b2_tit, SPLIT_TILE,
        ffn2, NTOK, D_, DFF_, 0);

    // 5) out = hid + LN(ffn2)
    ln_res_kernel<<<(NTOK + 3) / 4, 128>>>(hid, ffn2, ln_a_img, ln_b_img,
                                           ln_a_tit, ln_b_tit, out);
}

// round 7
// speedup vs baseline: 3.3793x; 1.1432x over previous
#include <cuda_runtime.h>
#include <math.h>
#include <stdint.h>

// Problem constants
#define B_   16
#define L_   50
#define P_   49
#define T_   20
#define D_   512
#define H_   8
#define DH_  64
#define DFF_ 2048
#define IMG_TOK (B_*L_*T_)   // 16000  (= 125 tiles of 128, exactly)
#define TIT_TOK (B_*L_*P_)   // 39200
#define NTOK (IMG_TOK + TIT_TOK)  // 55200
#define NEGV (-1000000000.0f)
#define EPS_ 1e-6f

// ---------------- scratch ----------------
__device__ uint32_t g_attn_t[NTOK * D_];              // attention out, tf32 bits
__device__ float    g_hid   [NTOK * D_];              // proj out fp32 (residual)
__device__ uint32_t g_hid_t [NTOK * D_];              // proj out tf32 (FFN1 input)
__device__ uint32_t g_ffn1_t[(size_t)NTOK * DFF_];    // gelu out tf32 (FFN2 input)
__device__ float    g_ffn2  [NTOK * D_];              // FFN2 out fp32 (LN input)

// pre-converted weights (tf32 bits), packed segments
#define WOFF_PROJ 0
#define WOFF_W1I  (512*512)
#define WOFF_W1T  (WOFF_W1I + 2048*512)
#define WOFF_W2I  (WOFF_W1T + 2048*512)
#define WOFF_W2T  (WOFF_W2I + 512*2048)
#define WTOTAL    (WOFF_W2T + 512*2048)   // 4456448
__device__ uint32_t g_wbuf[WTOTAL];

__device__ __forceinline__ uint32_t f2tf32(float f) {
    uint32_t r; asm("cvt.rna.tf32.f32 %0, %1;" : "=r"(r) : "f"(f)); return r;
}
__device__ __forceinline__ float gelu_t(float x) {
    float x3 = x * x * x;
    float u = 0.7978845608028654f * (x + 0.044715f * x3);
    return 0.5f * x * (1.f + tanhf(u));
}
__device__ __forceinline__ void mma_tf32(float* c, const uint32_t* a, const uint32_t* b) {
    asm volatile(
        "mma.sync.aligned.m16n8k8.row.col.f32.tf32.tf32.f32 "
        "{%0,%1,%2,%3}, {%4,%5,%6,%7}, {%8,%9}, {%0,%1,%2,%3};"
        : "+f"(c[0]), "+f"(c[1]), "+f"(c[2]), "+f"(c[3])
        : "r"(a[0]), "r"(a[1]), "r"(a[2]), "r"(a[3]), "r"(b[0]), "r"(b[1]));
}
__device__ __forceinline__ void cp_async16(uint32_t dst, const void* src, uint32_t nbytes) {
    asm volatile("cp.async.cg.shared.global [%0], [%1], 16, %2;"
                 :: "r"(dst), "l"(src), "r"(nbytes));
}
__device__ __forceinline__ void cp_commit() {
    asm volatile("cp.async.commit_group;" ::: "memory");
}
template <int N>
__device__ __forceinline__ void cp_wait() {
    asm volatile("cp.async.wait_group %0;" :: "n"(N) : "memory");
}

// ---------------- weight pre-conversion (fp32 -> tf32 bits) ----------------
__global__ void __launch_bounds__(256) prep_w(
    const float* __restrict__ a0, const float* __restrict__ a1,
    const float* __restrict__ a2, const float* __restrict__ a3,
    const float* __restrict__ a4, uint32_t* __restrict__ o)
{
    size_t i = ((size_t)blockIdx.x * 256 + threadIdx.x) * 4;
    if (i >= WTOTAL) return;
    const float* src; size_t off;
    if      (i < WOFF_W1I) { src = a0; off = i; }
    else if (i < WOFF_W1T) { src = a1; off = i - WOFF_W1I; }
    else if (i < WOFF_W2I) { src = a2; off = i - WOFF_W1T; }
    else if (i < WOFF_W2T) { src = a3; off = i - WOFF_W2I; }
    else                   { src = a4; off = i - WOFF_W2T; }
    float4 v = *(const float4*)(src + off);
    uint4 u; u.x = f2tf32(v.x); u.y = f2tf32(v.y); u.z = f2tf32(v.z); u.w = f2tf32(v.w);
    *(uint4*)(o + i) = u;
}

// ---------------- tensor-core GEMM via mma.sync tf32 + cp.async ----------------
// Operands are pre-converted tf32 bit patterns: NO cvt in the kernel.
// C = A[M,K] @ Wsel[N,K]^T + bias (+GELU). Optional fp32 and tf32 outputs.
#define SROW 36                       // smem row stride (u32); row = 144 B, conflict-free
#define TILE_BYTES (128 * SROW * 4)   // 18432 B per matrix per buffer
#define MM_SMEM (4 * TILE_BYTES)      // 73728 B

__global__ void __launch_bounds__(256, 2) mma_gemm(
    const uint32_t* __restrict__ A,
    const uint32_t* __restrict__ W0, const float* __restrict__ b0,
    const uint32_t* __restrict__ W1, const float* __restrict__ b1,
    int split_tile,
    float* __restrict__ Cf, uint32_t* __restrict__ Ct,
    int M, int N, int K, int act)
{
    extern __shared__ uint32_t sh[];
    const uint32_t sm_base = (uint32_t)__cvta_generic_to_shared(sh);
    const uint32_t aU[2] = { sm_base,                  sm_base + TILE_BYTES };
    const uint32_t bU[2] = { sm_base + 2 * TILE_BYTES, sm_base + 3 * TILE_BYTES };
    const uint32_t* aF[2] = { sh,                      sh + TILE_BYTES / 4 };
    const uint32_t* bF[2] = { sh + 2 * TILE_BYTES / 4, sh + 3 * TILE_BYTES / 4 };

    const int tid = threadIdx.x;
    const int m0 = blockIdx.y * 128, n0 = blockIdx.x * 128;
    const uint32_t* W  = (blockIdx.y < split_tile) ? W0 : W1;
    const float* bias  = (blockIdx.y < split_tile) ? b0 : b1;

    const int w = tid >> 5, lane = tid & 31;
    const int wm = w & 3, wn = w >> 2;          // warp tile: rows wm*32, cols wn*64
    const int group = lane >> 2, quad = lane & 3;

    const int lrow0 = tid >> 3;        // copy mapping: rows lrow0 + t*32
    const int lc4   = tid & 7;         // 16B column

    float acc[2][8][4];
    #pragma unroll
    for (int i = 0; i < 2; i++)
        #pragma unroll
        for (int j = 0; j < 8; j++)
            #pragma unroll
            for (int q = 0; q < 4; q++) acc[i][j][q] = 0.f;

    const int nch = K >> 5;

    auto issue = [&](int buf, int kc) {
        #pragma unroll
        for (int t = 0; t < 4; t++) {
            int row = lrow0 + t * 32;
            uint32_t off = (uint32_t)(row * 144 + lc4 * 16);
            size_t arow = (m0 + row < M) ? (size_t)(m0 + row) : 0;
            cp_async16(aU[buf] + off, A + arow * K + kc + lc4 * 4,
                       (m0 + row < M) ? 16u : 0u);
            cp_async16(bU[buf] + off, W + (size_t)(n0 + row) * K + kc + lc4 * 4, 16u);
        }
        cp_commit();
    };

    auto compute = [&](int buf) {
        const uint32_t* ap = aF[buf];
        const uint32_t* bp = bF[buf];
        #pragma unroll
        for (int ks = 0; ks < 4; ks++) {
            const int k0 = ks * 8;
            uint32_t afr[2][4];
            #pragma unroll
            for (int mi = 0; mi < 2; mi++) {
                int r = wm * 32 + mi * 16 + group;
                afr[mi][0] = ap[(r    ) * SROW + k0 + quad];
                afr[mi][1] = ap[(r + 8) * SROW + k0 + quad];
                afr[mi][2] = ap[(r    ) * SROW + k0 + quad + 4];
                afr[mi][3] = ap[(r + 8) * SROW + k0 + quad + 4];
            }
            uint32_t bfr[8][2];
            #pragma unroll
            for (int ni = 0; ni < 8; ni++) {
                int n = wn * 64 + ni * 8 + group;
                bfr[ni][0] = bp[n * SROW + k0 + quad];
                bfr[ni][1] = bp[n * SROW + k0 + quad + 4];
            }
            #pragma unroll
            for (int mi = 0; mi < 2; mi++)
                #pragma unroll
                for (int ni = 0; ni < 8; ni++)
                    mma_tf32(acc[mi][ni], afr[mi], bfr[ni]);
        }
    };

    // prologue
    issue(0, 0);

    for (int c = 0; c < nch; c++) {
        int cur = c & 1;
        if (c + 1 < nch) {
            issue(cur ^ 1, (c + 1) << 5);
            cp_wait<1>();            // chunk c landed; chunk c+1 still in flight
        } else {
            cp_wait<0>();
        }
        __syncthreads();
        compute(cur);
        __syncthreads();             // all warps done with buf[cur] before overwrite
    }

    // epilogue: bias + optional GELU; fp32 and/or tf32 outputs
    #pragma unroll
    for (int ni = 0; ni < 8; ni++) {
        int cc = n0 + wn * 64 + ni * 8 + quad * 2;
        float2 b2 = *(const float2*)(bias + cc);
        #pragma unroll
        for (int mi = 0; mi < 2; mi++) {
            #pragma unroll
            for (int half = 0; half < 2; half++) {
                int r = m0 + wm * 32 + mi * 16 + half * 8 + group;
                if (r >= M) continue;
                float2 v;
                v.x = acc[mi][ni][half * 2 + 0] + b2.x;
                v.y = acc[mi][ni][half * 2 + 1] + b2.y;
                if (act) { v.x = gelu_t(v.x); v.y = gelu_t(v.y); }
                if (Cf) *(float2*)(Cf + (size_t)r * N + cc) = v;
                if (Ct) {
                    uint2 u; u.x = f2tf32(v.x); u.y = f2tf32(v.y);
                    *(uint2*)(Ct + (size_t)r * N + cc) = u;
                }
            }
        }
    }
}

// ---------------- attention kernel (fp32 compute, tf32 output) ----------------
__global__ void __launch_bounds__(256) attn_kernel(
    const float* __restrict__ img, const float* __restrict__ title,
    const int* __restrict__ mask,
    const float* __restrict__ scale_img, const float* __restrict__ scale_title,
    uint32_t* __restrict__ attn)
{
    int blk = blockIdx.x;
    int h  = blk % H_;
    int bl = blk / H_;

    const float* imgp = img   + (size_t)bl * P_ * D_ + h * DH_;
    const float* titp = title + (size_t)bl * T_ * D_ + h * DH_;
    const int*   mp   = mask  + bl * T_;

    __shared__ float s_img[P_][DH_ + 1];
    __shared__ float s_tit[T_][DH_ + 1];
    __shared__ float s_raw [P_][T_];
    __shared__ float s_pimg[P_][T_];
    __shared__ float s_ptit[T_][P_];
    __shared__ float s_mask[T_];

    int tid = threadIdx.x;

    for (int i = tid; i < P_ * DH_; i += 256) {
        int p = i / DH_, d = i % DH_;
        s_img[p][d] = imgp[(size_t)p * D_ + d];
    }
    for (int i = tid; i < T_ * DH_; i += 256) {
        int t = i / DH_, d = i % DH_;
        s_tit[t][d] = titp[(size_t)t * D_ + d];
    }
    if (tid < T_) s_mask[tid] = (float)mp[tid];
    __syncthreads();

    for (int i = tid; i < P_ * T_; i += 256) {
        int p = i / T_, t = i % T_;
        float acc = 0.f;
        #pragma unroll
        for (int d = 0; d < DH_; d++) acc += s_img[p][d] * s_tit[t][d];
        s_raw[p][t] = acc * 0.125f;
    }
    __syncthreads();

    if (tid < P_) {
        int p = tid;
        float sc = scale_img[h * P_ + p];
        float row[T_];
        float mx = -INFINITY;
        #pragma unroll
        for (int t = 0; t < T_; t++) {
            float v = (s_mask[t] != 0.f) ? s_raw[p][t] * sc : NEGV;
            row[t] = v;
            mx = fmaxf(mx, v);
        }
        float sum = 0.f;
        #pragma unroll
        for (int t = 0; t < T_; t++) { float e = expf(row[t] - mx); row[t] = e; sum += e; }
        float inv = 1.f / sum;
        #pragma unroll
        for (int t = 0; t < T_; t++) s_pimg[p][t] = row[t] * inv;
    }
    if (tid >= 64 && tid < 64 + T_) {
        int t = tid - 64;
        float sc = scale_title[h * T_ + t];
        bool dead = (s_mask[t] == 0.f);
        float mx = -INFINITY;
        for (int p = 0; p < P_; p++) {
            float v = dead ? NEGV : s_raw[p][t] * sc;
            mx = fmaxf(mx, v);
        }
        float sum = 0.f;
        for (int p = 0; p < P_; p++) {
            float v = dead ? NEGV : s_raw[p][t] * sc;
            float e = expf(v - mx);
            s_ptit[t][p] = e;
            sum += e;
        }
        float inv = 1.f / sum;
        for (int p = 0; p < P_; p++) s_ptit[t][p] *= inv;
    }
    __syncthreads();

    uint32_t* out_img = attn + (size_t)bl * T_ * D_ + h * DH_;
    for (int i = tid; i < T_ * DH_; i += 256) {
        int t = i / DH_, d = i % DH_;
        float acc = 0.f;
        #pragma unroll 7
        for (int p = 0; p < P_; p++) acc += s_ptit[t][p] * s_img[p][d];
        out_img[(size_t)t * D_ + d] = f2tf32(acc);
    }
    uint32_t* out_tit = attn + (size_t)IMG_TOK * D_ + (size_t)bl * P_ * D_ + h * DH_;
    for (int i = tid; i < P_ * DH_; i += 256) {
        int p = i / DH_, d = i % DH_;
        float acc = 0.f;
        #pragma unroll
        for (int t = 0; t < T_; t++) acc += s_pimg[p][t] * s_tit[t][d];
        out_tit[(size_t)p * D_ + d] = f2tf32(acc);
    }
}

// ---------------- residual + LayerNorm: 4 warps/block, one token per warp ----------------
__global__ void __launch_bounds__(128) ln_res_kernel(
    const float* __restrict__ hid, const float* __restrict__ ffn,
    const float* __restrict__ aimg, const float* __restrict__ bimg,
    const float* __restrict__ atit, const float* __restrict__ btit,
    float* __restrict__ out)
{
    int tok = blockIdx.x * 4 + (threadIdx.x >> 5);
    if (tok >= NTOK) return;
    const float* a  = (tok < IMG_TOK) ? aimg : atit;
    const float* bb = (tok < IMG_TOK) ? bimg : btit;
    const float* x  = ffn + (size_t)tok * D_;
    const float* hh = hid + (size_t)tok * D_;
    float* o        = out + (size_t)tok * D_;

    int lane = threadIdx.x & 31;
    float v[16];
    float s = 0.f;
    #pragma unroll
    for (int i = 0; i < 4; i++) {
        float4 t4 = *(const float4*)(x + lane * 4 + i * 128);
        v[i*4+0] = t4.x; v[i*4+1] = t4.y; v[i*4+2] = t4.z; v[i*4+3] = t4.w;
        s += t4.x + t4.y + t4.z + t4.w;
    }
    #pragma unroll
    for (int off = 16; off > 0; off >>= 1) s += __shfl_xor_sync(0xffffffffu, s, off);
    float mean = s * (1.f / 512.f);

    float sq = 0.f;
    #pragma unroll
    for (int i = 0; i < 16; i++) { float d = v[i] - mean; sq += d * d; }
    #pragma unroll
    for (int off = 16; off > 0; off >>= 1) sq += __shfl_xor_sync(0xffffffffu, sq, off);
    float stdv = sqrtf(sq * (1.f / 511.f));
    float inv = 1.f / (stdv + EPS_);

    #pragma unroll
    for (int i = 0; i < 4; i++) {
        int c0 = lane * 4 + i * 128;
        float4 a4 = *(const float4*)(a  + c0);
        float4 b4 = *(const float4*)(bb + c0);
        float4 h4 = *(const float4*)(hh + c0);
        float4 r;
        r.x = h4.x + a4.x * (v[i*4+0] - mean) * inv + b4.x;
        r.y = h4.y + a4.y * (v[i*4+1] - mean) * inv + b4.y;
        r.z = h4.z + a4.z * (v[i*4+2] - mean) * inv + b4.z;
        r.w = h4.w + a4.w * (v[i*4+3] - mean) * inv + b4.w;
        *(float4*)(o + c0) = r;
    }
}

// ---------------- launch ----------------
#define MTILES ((NTOK + 127) / 128)      // 432
#define SPLIT_TILE (IMG_TOK / 128)       // 125 (exact)

extern "C" void kernel_launch(void* const* d_in, const int* in_sizes, int n_in,
                              void* d_out, int out_size)
{
    const float* img         = (const float*)d_in[0];
    const float* title       = (const float*)d_in[1];
    const int*   mask        = (const int*)  d_in[2];
    const float* scale_img   = (const float*)d_in[3];
    const float* scale_title = (const float*)d_in[4];
    const float* w_proj      = (const float*)d_in[5];
    const float* b_proj      = (const float*)d_in[6];
    const float* w1_img      = (const float*)d_in[7];
    const float* b1_img      = (const float*)d_in[8];
    const float* w2_img      = (const float*)d_in[9];
    const float* b2_img      = (const float*)d_in[10];
    const float* w1_tit      = (const float*)d_in[11];
    const float* b1_tit      = (const float*)d_in[12];
    const float* w2_tit      = (const float*)d_in[13];
    const float* b2_tit      = (const float*)d_in[14];
    const float* ln_a_img    = (const float*)d_in[15];
    const float* ln_b_img    = (const float*)d_in[16];
    const float* ln_a_tit    = (const float*)d_in[17];
    const float* ln_b_tit    = (const float*)d_in[18];
    float* out = (float*)d_out;

    uint32_t *attn_t, *hid_t, *ffn1_t, *wbuf;
    float *hid, *ffn2;
    cudaGetSymbolAddress((void**)&attn_t, g_attn_t);
    cudaGetSymbolAddress((void**)&hid,    g_hid);
    cudaGetSymbolAddress((void**)&hid_t,  g_hid_t);
    cudaGetSymbolAddress((void**)&ffn1_t, g_ffn1_t);
    cudaGetSymbolAddress((void**)&ffn2,   g_ffn2);
    cudaGetSymbolAddress((void**)&wbuf,   g_wbuf);

    cudaFuncSetAttribute(mma_gemm, cudaFuncAttributeMaxDynamicSharedMemorySize, MM_SMEM);

    // 0) weights -> tf32 bits
    prep_w<<<(WTOTAL / 4 + 255) / 256, 256>>>(w_proj, w1_img, w1_tit, w2_img, w2_tit, wbuf);

    // 1) attention (writes tf32)
    attn_kernel<<<B_ * L_ * H_, 256>>>(img, title, mask, scale_img, scale_title, attn_t);

    // 2) shared projection: fp32 hid (residual) + tf32 hid_t (FFN1 input)
    mma_gemm<<<dim3(D_ / 128, MTILES), 256, MM_SMEM>>>(
        attn_t, wbuf + WOFF_PROJ, b_proj, wbuf + WOFF_PROJ, b_proj, MTILES,
        hid, hid_t, NTOK, D_, D_, 0);

    // 3) FFN1 (+GELU), both branches, tf32 output only
    mma_gemm<<<dim3(DFF_ / 128, MTILES), 256, MM_SMEM>>>(
        hid_t, wbuf + WOFF_W1I, b1_img, wbuf + WOFF_W1T, b1_tit, SPLIT_TILE,
        (float*)nullptr, ffn1_t, NTOK, DFF_, D_, 1);

    // 4) FFN2, both branches, fp32 output only
    mma_gemm<<<dim3(D_ / 128, MTILES), 256, MM_SMEM>>>(
        ffn1_t, wbuf + WOFF_W2I, b2_img, wbuf + WOFF_W2T, b2_tit, SPLIT_TILE,
        ffn2, (uint32_t*)nullptr, NTOK, D_, DFF_, 0);

    // 5) out = hid + LN(ffn2)
    ln_res_kernel<<<(NTOK + 3) / 4, 128>>>(hid, ffn2, ln_a_img, ln_b_img,
                                           ln_a_tit, ln_b_tit, out);
}